// round 8
// baseline (speedup 1.0000x reference)
#include <cuda_runtime.h>
#include <cstdint>
#include <math.h>

// ----------------------------------------------------------------------------
// GraphSAGE (2-layer weighted-mean SAGEConv) on sm_100a.
//   L1: agg = mean_w(X[src]); H = relu(l2norm(agg@Wl1 + X@Wr1 + b1)) * jax-dropout
//   L2: agg2 = mean_w(H[src]); Z = agg2@Wl2 + H@Wr2 + b2; out = log_softmax(Z)
// Edge index A is INT32 (JAX x64-disabled downgrades the reference's int64).
// Dropout reproduces jax.random.bernoulli(key(42), 0.5) under the modern
// PARTITIONABLE threefry: per-element 64-bit counter (hi,lo)=(0,i),
// word = out0 ^ out1, keep <=> top bit == 0.
// ----------------------------------------------------------------------------

#define N_NODES 100000
#define N_EDGES 1600000
#define D_IN    32
#define D_HID   64
#define D_OUT   40
#define MASK_N  (N_NODES * D_HID)   // 6.4M mask elements

// Scratch (device globals: allocation-free rule). float4-typed => 16B aligned,
// so .v4 reductions / vector loads are legal.
__device__ float4        g_agg1[N_NODES * (D_IN / 4)];    // 12.8 MB
__device__ float4        g_deg4[N_NODES / 4];             // 0.4 MB
__device__ float4        g_H   [N_NODES * (D_HID / 4)];   // 25.6 MB
__device__ float4        g_agg2[N_NODES * (D_HID / 4)];   // 25.6 MB
__device__ unsigned char g_mask[MASK_N];                  // 6.4 MB

// ---------------------------------------------------------------------------
// 16-byte no-return reduction (arch-specific PTX, sm_90a/sm_100a+).
// Explicit cvta.to.global so red.global gets a true global-space address.
// ---------------------------------------------------------------------------
__device__ __forceinline__ void red_add_v4(float4* p, float4 v) {
    asm volatile(
        "{\n\t"
        ".reg .u64 gp;\n\t"
        "cvta.to.global.u64 gp, %0;\n\t"
        "red.global.add.v4.f32 [gp], {%1, %2, %3, %4};\n\t"
        "}"
        :: "l"(p), "f"(v.x), "f"(v.y), "f"(v.z), "f"(v.w)
        : "memory");
}

// ---------------------------------------------------------------------------
// threefry2x32, key = (0, 42) (jax.random.key(42)), PARTITIONABLE counters:
// element i uses counter pair (x0, x1) = (0, i); 32-bit word = y0 ^ y1.
// ---------------------------------------------------------------------------
__device__ __forceinline__ uint32_t rotl32(uint32_t x, int r) {
    return (x << r) | (x >> (32 - r));
}

__global__ void mask_kernel() {
    int i = blockIdx.x * blockDim.x + threadIdx.x;
    if (i >= MASK_N) return;

    const uint32_t ks0 = 0u;
    const uint32_t ks1 = 42u;
    const uint32_t ks2 = 0x1BD11BDAu ^ 0u ^ 42u;

    uint32_t x0 = 0u;            // hi32 of 64-bit counter (0 for i < 2^32)
    uint32_t x1 = (uint32_t)i;   // lo32

    x0 += ks0; x1 += ks1;

#define TF_ROUND(r) { x0 += x1; x1 = rotl32(x1, (r)); x1 ^= x0; }
    TF_ROUND(13) TF_ROUND(15) TF_ROUND(26) TF_ROUND(6)
    x0 += ks1; x1 += ks2 + 1u;
    TF_ROUND(17) TF_ROUND(29) TF_ROUND(16) TF_ROUND(24)
    x0 += ks2; x1 += ks0 + 2u;
    TF_ROUND(13) TF_ROUND(15) TF_ROUND(26) TF_ROUND(6)
    x0 += ks0; x1 += ks1 + 3u;
    TF_ROUND(17) TF_ROUND(29) TF_ROUND(16) TF_ROUND(24)
    x0 += ks1; x1 += ks2 + 4u;
    TF_ROUND(13) TF_ROUND(15) TF_ROUND(26) TF_ROUND(6)
    x0 += ks2; x1 += ks0 + 5u;
#undef TF_ROUND

    uint32_t bits = x0 ^ x1;     // partitionable 32-bit output
    // uniform(bits) < 0.5  <=>  top bit of bits == 0
    g_mask[i] = (unsigned char)((bits >> 31) ^ 1u);
}

// ---------------------------------------------------------------------------
// zero scratch accumulators
// ---------------------------------------------------------------------------
__global__ void zero_kernel() {
    int i      = blockIdx.x * blockDim.x + threadIdx.x;
    int stride = gridDim.x * blockDim.x;
    float4 z = make_float4(0.f, 0.f, 0.f, 0.f);
    for (int j = i; j < 800000;  j += stride) g_agg1[j] = z;
    for (int j = i; j < 1600000; j += stride) g_agg2[j] = z;
    for (int j = i; j < 25000;   j += stride) g_deg4[j] = z;
}

// ---------------------------------------------------------------------------
// layer-1 edge scatter: agg1[dst] += X[src]*w (8 x float4 chunks), deg[dst] += 1
// 8 threads per edge; indices loaded once per edge, broadcast by shuffle.
// ---------------------------------------------------------------------------
__global__ void edge1_kernel(const float* __restrict__ X,
                             const int* __restrict__ A,
                             const float* __restrict__ W) {
    int t = blockIdx.x * blockDim.x + threadIdx.x;
    int e = t >> 3;
    int c = t & 7;
    if (e >= N_EDGES) return;
    int lane = threadIdx.x & 31;
    int srcLane = lane & ~7;

    int s = 0, d = 0; float w = 0.f;
    if (c == 0) {
        s = A[e];
        d = A[N_EDGES + e];
        w = W[e];
    }
    s = __shfl_sync(0xffffffffu, s, srcLane);
    d = __shfl_sync(0xffffffffu, d, srcLane);
    w = __shfl_sync(0xffffffffu, w, srcLane);

    float4 xv = ((const float4*)X)[s * 8 + c];
    float4 m = make_float4(xv.x * w, xv.y * w, xv.z * w, xv.w * w);
    red_add_v4(&g_agg1[d * 8 + c], m);
    if (c == 0) atomicAdd((float*)g_deg4 + d, 1.0f);
}

// ---------------------------------------------------------------------------
// layer-1 node update: H = dropout(relu(l2norm(mean@Wl1 + X@Wr1 + b1)))
// one warp per node; lane owns output cols (lane, lane+32)
// ---------------------------------------------------------------------------
__global__ void node1_kernel(const float* __restrict__ X,
                             const float* __restrict__ Wl1,
                             const float* __restrict__ Wr1,
                             const float* __restrict__ b1) {
    __shared__ float sWl[D_IN * D_HID];   // 8 KB
    __shared__ float sWr[D_IN * D_HID];   // 8 KB
    __shared__ float sA[8][D_IN];
    __shared__ float sX[8][D_IN];

    int tid = threadIdx.x;
    for (int i = tid; i < D_IN * D_HID; i += 256) {
        sWl[i] = Wl1[i];
        sWr[i] = Wr1[i];
    }
    int warp = tid >> 5, lane = tid & 31;
    int node = blockIdx.x * 8 + warp;
    __syncthreads();
    if (node >= N_NODES) return;

    const float* agg1 = (const float*)g_agg1;
    const float* deg  = (const float*)g_deg4;

    float inv = 1.0f / fmaxf(deg[node], 1.0f);
    sA[warp][lane] = agg1[node * D_IN + lane] * inv;
    sX[warp][lane] = X[node * D_IN + lane];
    __syncwarp();

    float acc0 = b1[lane];
    float acc1 = b1[lane + 32];
#pragma unroll
    for (int k = 0; k < D_IN; k++) {
        float av = sA[warp][k];
        float xv = sX[warp][k];
        acc0 += av * sWl[k * D_HID + lane]      + xv * sWr[k * D_HID + lane];
        acc1 += av * sWl[k * D_HID + lane + 32] + xv * sWr[k * D_HID + lane + 32];
    }
    float ss = acc0 * acc0 + acc1 * acc1;
#pragma unroll
    for (int o = 16; o > 0; o >>= 1) ss += __shfl_xor_sync(0xffffffffu, ss, o);
    float scale = rsqrtf(fmaxf(ss, 1e-24f));

    float h0 = fmaxf(acc0 * scale, 0.0f);
    float h1 = fmaxf(acc1 * scale, 0.0f);
    int base = node * D_HID;
    h0 = g_mask[base + lane]      ? 2.0f * h0 : 0.0f;
    h1 = g_mask[base + lane + 32] ? 2.0f * h1 : 0.0f;
    float* H = (float*)g_H;
    H[base + lane]      = h0;
    H[base + lane + 32] = h1;
}

// ---------------------------------------------------------------------------
// layer-2 edge scatter: agg2[dst] += H[src]*w (16 x float4 chunks)
// ---------------------------------------------------------------------------
__global__ void edge2_kernel(const int* __restrict__ A,
                             const float* __restrict__ W) {
    int t = blockIdx.x * blockDim.x + threadIdx.x;
    int e = t >> 4;
    int c = t & 15;
    if (e >= N_EDGES) return;
    int lane = threadIdx.x & 31;
    int srcLane = lane & 16;

    int s = 0, d = 0; float w = 0.f;
    if (c == 0) {
        s = A[e];
        d = A[N_EDGES + e];
        w = W[e];
    }
    s = __shfl_sync(0xffffffffu, s, srcLane);
    d = __shfl_sync(0xffffffffu, d, srcLane);
    w = __shfl_sync(0xffffffffu, w, srcLane);

    float4 hv = g_H[s * 16 + c];
    float4 m = make_float4(hv.x * w, hv.y * w, hv.z * w, hv.w * w);
    red_add_v4(&g_agg2[d * 16 + c], m);
}

// ---------------------------------------------------------------------------
// layer-2 node update + log_softmax. one warp per node.
// lane owns z[lane]; lanes 0..7 additionally own z[lane+32]. 40 outputs.
// ---------------------------------------------------------------------------
__global__ void node2_kernel(const float* __restrict__ Wl2,
                             const float* __restrict__ Wr2,
                             const float* __restrict__ b2,
                             float* __restrict__ out) {
    __shared__ float sWl[D_HID * 64];   // padded to 64 cols, 16 KB
    __shared__ float sWr[D_HID * 64];   // 16 KB
    __shared__ float sA[8][D_HID];
    __shared__ float sH[8][D_HID];

    int tid = threadIdx.x;
    for (int i = tid; i < D_HID * 64; i += 256) {
        int k = i >> 6, j = i & 63;
        sWl[i] = (j < D_OUT) ? Wl2[k * D_OUT + j] : 0.0f;
        sWr[i] = (j < D_OUT) ? Wr2[k * D_OUT + j] : 0.0f;
    }
    int warp = tid >> 5, lane = tid & 31;
    int node = blockIdx.x * 8 + warp;
    __syncthreads();
    if (node >= N_NODES) return;

    const float* agg2 = (const float*)g_agg2;
    const float* H    = (const float*)g_H;
    const float* deg  = (const float*)g_deg4;

    float inv = 1.0f / fmaxf(deg[node], 1.0f);
    int base = node * D_HID;
    sA[warp][lane]      = agg2[base + lane] * inv;
    sA[warp][lane + 32] = agg2[base + lane + 32] * inv;
    sH[warp][lane]      = H[base + lane];
    sH[warp][lane + 32] = H[base + lane + 32];
    __syncwarp();

    float z0 = b2[lane];                       // lane < 32 < 40: always valid
    float z1 = (lane < 8) ? b2[lane + 32] : 0.0f;
#pragma unroll
    for (int k = 0; k < D_HID; k++) {
        float av = sA[warp][k];
        float hv = sH[warp][k];
        z0 += av * sWl[k * 64 + lane]      + hv * sWr[k * 64 + lane];
        z1 += av * sWl[k * 64 + lane + 32] + hv * sWr[k * 64 + lane + 32];
    }

    // log_softmax over 40 valid entries
    float m = (lane < 8) ? fmaxf(z0, z1) : z0;
#pragma unroll
    for (int o = 16; o > 0; o >>= 1) m = fmaxf(m, __shfl_xor_sync(0xffffffffu, m, o));
    float ssum = expf(z0 - m) + ((lane < 8) ? expf(z1 - m) : 0.0f);
#pragma unroll
    for (int o = 16; o > 0; o >>= 1) ssum += __shfl_xor_sync(0xffffffffu, ssum, o);
    float lse = m + logf(ssum);

    out[node * D_OUT + lane] = z0 - lse;
    if (lane < 8) out[node * D_OUT + 32 + lane] = z1 - lse;
}

// ---------------------------------------------------------------------------
extern "C" void kernel_launch(void* const* d_in, const int* in_sizes, int n_in,
                              void* d_out, int out_size) {
    const float* X   = (const float*)d_in[0];
    const int*   A   = (const int*)d_in[1];     // int32! (JAX x64 disabled)
    const float* W   = (const float*)d_in[2];
    const float* Wl1 = (const float*)d_in[3];
    const float* Wr1 = (const float*)d_in[4];
    const float* b1  = (const float*)d_in[5];
    const float* Wl2 = (const float*)d_in[6];
    const float* Wr2 = (const float*)d_in[7];
    const float* b2  = (const float*)d_in[8];
    float*       out = (float*)d_out;

    mask_kernel<<<MASK_N / 256 + 1, 256>>>();
    zero_kernel<<<2048, 256>>>();
    edge1_kernel<<<(N_EDGES * 8) / 256, 256>>>(X, A, W);
    node1_kernel<<<(N_NODES + 7) / 8, 256>>>(X, Wl1, Wr1, b1);
    edge2_kernel<<<(N_EDGES * 16) / 256, 256>>>(A, W);
    node2_kernel<<<(N_NODES + 7) / 8, 256>>>(Wl2, Wr2, b2, out);
}

// round 9
// speedup vs baseline: 1.4288x; 1.4288x over previous
#include <cuda_runtime.h>
#include <cstdint>
#include <math.h>

// ----------------------------------------------------------------------------
// GraphSAGE (2-layer weighted-mean SAGEConv) on sm_100a.
// L1: agg1 = sum(w*X[src]); H = dropout(relu(l2norm((agg1/deg)@Wl1 + X@Wr1 + b1)))
// P  = H@Wl2  (linearity: mean(w*H)@Wl2 == mean(w*P))
// L2: aggP = sum(w*P[src]); Z = aggP/deg + H@Wr2 + b2; out = log_softmax(Z)
// A is int32. Dropout = jax partitionable threefry, key(42): counter (0,i),
// word = y0^y1, keep <=> top bit == 0.
// ----------------------------------------------------------------------------

#define N_NODES 100000
#define N_EDGES 1600000
#define D_IN    32
#define D_HID   64
#define D_OUT   40
#define MASK_N  (N_NODES * D_HID)

// Scratch (device globals). float4-typed => 16B aligned.
__device__ float4        g_agg1[N_NODES * (D_IN / 4)];    // 12.8 MB
__device__ float4        g_deg4[N_NODES / 4];             // 0.4 MB
__device__ float4        g_H   [N_NODES * (D_HID / 4)];   // 25.6 MB
__device__ float4        g_P   [N_NODES * 10];            // 16 MB (40 f/node)
__device__ float4        g_aggP[N_NODES * 10];            // 16 MB
__device__ unsigned char g_mask[MASK_N];                  // 6.4 MB

// ---------------------------------------------------------------------------
__device__ __forceinline__ void red_add_v4(float4* p, float4 v) {
    asm volatile(
        "{\n\t"
        ".reg .u64 gp;\n\t"
        "cvta.to.global.u64 gp, %0;\n\t"
        "red.global.add.v4.f32 [gp], {%1, %2, %3, %4};\n\t"
        "}"
        :: "l"(p), "f"(v.x), "f"(v.y), "f"(v.z), "f"(v.w)
        : "memory");
}

// ---------------------------------------------------------------------------
// threefry2x32 partitionable, key (0,42): counter (0,i), word = y0^y1.
// 4 independent chains per thread for ILP; one uchar4 store.
// ---------------------------------------------------------------------------
__device__ __forceinline__ uint32_t rotl32(uint32_t x, int r) {
    return __funnelshift_l(x, x, r);
}

__global__ void mask_kernel() {
    int t = blockIdx.x * blockDim.x + threadIdx.x;   // 1.6M threads
    uint32_t base = (uint32_t)t * 4u;
    if (base >= (uint32_t)MASK_N) return;

    const uint32_t ks0 = 0u;
    const uint32_t ks1 = 42u;
    const uint32_t ks2 = 0x1BD11BDAu ^ 0u ^ 42u;

    uint32_t a0 = ks0, a1 = ks0, a2 = ks0, a3 = ks0;
    uint32_t b0 = base + 0u + ks1, b1v = base + 1u + ks1;
    uint32_t b2v = base + 2u + ks1, b3 = base + 3u + ks1;

#define TF4(r) { \
    a0 += b0;  b0  = rotl32(b0,  (r)); b0  ^= a0; \
    a1 += b1v; b1v = rotl32(b1v, (r)); b1v ^= a1; \
    a2 += b2v; b2v = rotl32(b2v, (r)); b2v ^= a2; \
    a3 += b3;  b3  = rotl32(b3,  (r)); b3  ^= a3; }
#define INJ4(ka, kb, c) { \
    a0 += (ka); b0  += (kb) + (c); a1 += (ka); b1v += (kb) + (c); \
    a2 += (ka); b2v += (kb) + (c); a3 += (ka); b3  += (kb) + (c); }

    TF4(13) TF4(15) TF4(26) TF4(6)
    INJ4(ks1, ks2, 1u)
    TF4(17) TF4(29) TF4(16) TF4(24)
    INJ4(ks2, ks0, 2u)
    TF4(13) TF4(15) TF4(26) TF4(6)
    INJ4(ks0, ks1, 3u)
    TF4(17) TF4(29) TF4(16) TF4(24)
    INJ4(ks1, ks2, 4u)
    TF4(13) TF4(15) TF4(26) TF4(6)
    INJ4(ks2, ks0, 5u)
#undef TF4
#undef INJ4

    uchar4 m;
    m.x = (unsigned char)((((a0 ^ b0)  >> 31) ^ 1u) & 1u);
    m.y = (unsigned char)((((a1 ^ b1v) >> 31) ^ 1u) & 1u);
    m.z = (unsigned char)((((a2 ^ b2v) >> 31) ^ 1u) & 1u);
    m.w = (unsigned char)((((a3 ^ b3)  >> 31) ^ 1u) & 1u);
    ((uchar4*)g_mask)[t] = m;
}

// ---------------------------------------------------------------------------
__global__ void zero_kernel() {
    int i      = blockIdx.x * blockDim.x + threadIdx.x;
    int stride = gridDim.x * blockDim.x;
    float4 z = make_float4(0.f, 0.f, 0.f, 0.f);
    for (int j = i; j < 800000;  j += stride) g_agg1[j] = z;
    for (int j = i; j < 1000000; j += stride) g_aggP[j] = z;
    for (int j = i; j < 25000;   j += stride) g_deg4[j] = z;
}

// ---------------------------------------------------------------------------
// layer-1 edge scatter: agg1[dst] += X[src]*w (8 x float4), deg[dst] += 1.
// ---------------------------------------------------------------------------
__global__ void edge1_kernel(const float* __restrict__ X,
                             const int* __restrict__ A,
                             const float* __restrict__ W) {
    int t = blockIdx.x * blockDim.x + threadIdx.x;
    int e = t >> 3;
    int c = t & 7;
    if (e >= N_EDGES) return;
    int lane = threadIdx.x & 31;
    int srcLane = lane & ~7;

    int s = 0, d = 0; float w = 0.f;
    if (c == 0) {
        s = A[e];
        d = A[N_EDGES + e];
        w = W[e];
    }
    s = __shfl_sync(0xffffffffu, s, srcLane);
    d = __shfl_sync(0xffffffffu, d, srcLane);
    w = __shfl_sync(0xffffffffu, w, srcLane);

    float4 xv = ((const float4*)X)[s * 8 + c];
    float4 m = make_float4(xv.x * w, xv.y * w, xv.z * w, xv.w * w);
    red_add_v4(&g_agg1[d * 8 + c], m);
    if (c == 0) atomicAdd((float*)g_deg4 + d, 1.0f);
}

// ---------------------------------------------------------------------------
// layer-1 node update, 4 nodes per warp (32 nodes / 256-thread block).
// H = dropout(relu(l2norm((agg1/deg)@Wl1 + X@Wr1 + b1)))
// Weights staged as float2 pairs (col, col+32): one LDS.64 per matrix per k.
// ---------------------------------------------------------------------------
__global__ void node1_kernel(const float* __restrict__ X,
                             const float* __restrict__ Wl1,
                             const float* __restrict__ Wr1,
                             const float* __restrict__ b1) {
    __shared__ float2 sWl[D_IN * 32];     // [k][j] = (Wl[k][j], Wl[k][j+32]) 8KB
    __shared__ float2 sWr[D_IN * 32];     // 8KB
    __shared__ float2 sIn[32][D_IN];      // [nodeInBlk][k] = (a/deg, x) 8KB

    int tid  = threadIdx.x;
    int warp = tid >> 5, lane = tid & 31;

    for (int i = tid; i < D_IN * 32; i += 256) {
        int k = i >> 5, j = i & 31;
        sWl[i] = make_float2(Wl1[k * D_HID + j], Wl1[k * D_HID + j + 32]);
        sWr[i] = make_float2(Wr1[k * D_HID + j], Wr1[k * D_HID + j + 32]);
    }

    int nodeBase = blockIdx.x * 32 + warp * 4;       // grid 3125 -> exact
    const float* agg1 = (const float*)g_agg1;
    const float* deg  = (const float*)g_deg4;

#pragma unroll
    for (int nn = 0; nn < 4; nn++) {
        int node = nodeBase + nn;
        float inv = 1.0f / fmaxf(deg[node], 1.0f);
        float a = agg1[node * D_IN + lane] * inv;
        float x = X[node * D_IN + lane];
        sIn[warp * 4 + nn][lane] = make_float2(a, x);
    }
    __syncthreads();

    float bb0 = b1[lane], bb1 = b1[lane + 32];
    float acc0[4], acc1[4];
#pragma unroll
    for (int nn = 0; nn < 4; nn++) { acc0[nn] = bb0; acc1[nn] = bb1; }

#pragma unroll
    for (int k = 0; k < D_IN; k++) {
        float2 wl = sWl[k * 32 + lane];
        float2 wr = sWr[k * 32 + lane];
#pragma unroll
        for (int nn = 0; nn < 4; nn++) {
            float2 ax = sIn[warp * 4 + nn][k];
            acc0[nn] += ax.x * wl.x + ax.y * wr.x;
            acc1[nn] += ax.x * wl.y + ax.y * wr.y;
        }
    }

    float* H = (float*)g_H;
#pragma unroll
    for (int nn = 0; nn < 4; nn++) {
        float ss = acc0[nn] * acc0[nn] + acc1[nn] * acc1[nn];
#pragma unroll
        for (int o = 16; o > 0; o >>= 1) ss += __shfl_xor_sync(0xffffffffu, ss, o);
        float scale = rsqrtf(fmaxf(ss, 1e-24f));

        float h0 = fmaxf(acc0[nn] * scale, 0.0f);
        float h1 = fmaxf(acc1[nn] * scale, 0.0f);
        int base = (nodeBase + nn) * D_HID;
        h0 = g_mask[base + lane]      ? 2.0f * h0 : 0.0f;
        h1 = g_mask[base + lane + 32] ? 2.0f * h1 : 0.0f;
        H[base + lane]      = h0;
        H[base + lane + 32] = h1;
    }
}

// ---------------------------------------------------------------------------
// P = H @ Wl2  (per node: 64 -> 40). 4 nodes/warp, paired weights.
// ---------------------------------------------------------------------------
__global__ void pmul_kernel(const float* __restrict__ Wl2) {
    __shared__ float2 sW[D_HID * 32];     // [k][j] = (W[k][j], j+32<40?W[k][j+32]:0) 16KB
    __shared__ float  sH[32][D_HID];      // 8KB

    int tid  = threadIdx.x;
    int warp = tid >> 5, lane = tid & 31;

    for (int i = tid; i < D_HID * 32; i += 256) {
        int k = i >> 5, j = i & 31;
        float w0 = Wl2[k * D_OUT + j];
        float w1 = (j + 32 < D_OUT) ? Wl2[k * D_OUT + j + 32] : 0.0f;
        sW[i] = make_float2(w0, w1);
    }

    int nodeBase = blockIdx.x * 32 + warp * 4;
    const float* H = (const float*)g_H;
#pragma unroll
    for (int nn = 0; nn < 4; nn++) {
        int node = nodeBase + nn;
        sH[warp * 4 + nn][lane]      = H[node * D_HID + lane];
        sH[warp * 4 + nn][lane + 32] = H[node * D_HID + lane + 32];
    }
    __syncthreads();

    float p0[4] = {0.f, 0.f, 0.f, 0.f};
    float p1[4] = {0.f, 0.f, 0.f, 0.f};
#pragma unroll
    for (int k = 0; k < D_HID; k++) {
        float2 w = sW[k * 32 + lane];
#pragma unroll
        for (int nn = 0; nn < 4; nn++) {
            float h = sH[warp * 4 + nn][k];
            p0[nn] += h * w.x;
            p1[nn] += h * w.y;
        }
    }

    float* P = (float*)g_P;
#pragma unroll
    for (int nn = 0; nn < 4; nn++) {
        int base = (nodeBase + nn) * D_OUT;
        P[base + lane] = p0[nn];
        if (lane < 8) P[base + 32 + lane] = p1[nn];
    }
}

// ---------------------------------------------------------------------------
// layer-2 edge scatter on P: aggP[dst] += P[src]*w (10 x float4 chunks,
// 16 threads/edge, chunks c>=10 idle).
// ---------------------------------------------------------------------------
__global__ void edge2_kernel(const int* __restrict__ A,
                             const float* __restrict__ W) {
    int t = blockIdx.x * blockDim.x + threadIdx.x;
    int e = t >> 4;
    int c = t & 15;
    if (e >= N_EDGES) return;
    int lane = threadIdx.x & 31;
    int srcLane = lane & 16;

    int s = 0, d = 0; float w = 0.f;
    if (c == 0) {
        s = A[e];
        d = A[N_EDGES + e];
        w = W[e];
    }
    s = __shfl_sync(0xffffffffu, s, srcLane);
    d = __shfl_sync(0xffffffffu, d, srcLane);
    w = __shfl_sync(0xffffffffu, w, srcLane);

    if (c < 10) {
        float4 pv = g_P[s * 10 + c];
        float4 m = make_float4(pv.x * w, pv.y * w, pv.z * w, pv.w * w);
        red_add_v4(&g_aggP[d * 10 + c], m);
    }
}

// ---------------------------------------------------------------------------
// layer-2 node update: Z = aggP/deg + H@Wr2 + b2; out = log_softmax(Z).
// 4 nodes/warp. lane owns col lane; lanes 0..7 also own col lane+32.
// ---------------------------------------------------------------------------
__global__ void node2_kernel(const float* __restrict__ Wr2,
                             const float* __restrict__ b2,
                             float* __restrict__ out) {
    __shared__ float2 sW[D_HID * 32];     // 16KB
    __shared__ float  sH[32][D_HID];      // 8KB

    int tid  = threadIdx.x;
    int warp = tid >> 5, lane = tid & 31;

    for (int i = tid; i < D_HID * 32; i += 256) {
        int k = i >> 5, j = i & 31;
        float w0 = Wr2[k * D_OUT + j];
        float w1 = (j + 32 < D_OUT) ? Wr2[k * D_OUT + j + 32] : 0.0f;
        sW[i] = make_float2(w0, w1);
    }

    int nodeBase = blockIdx.x * 32 + warp * 4;
    const float* H = (const float*)g_H;
#pragma unroll
    for (int nn = 0; nn < 4; nn++) {
        int node = nodeBase + nn;
        sH[warp * 4 + nn][lane]      = H[node * D_HID + lane];
        sH[warp * 4 + nn][lane + 32] = H[node * D_HID + lane + 32];
    }
    __syncthreads();

    float z0[4] = {0.f, 0.f, 0.f, 0.f};
    float z1[4] = {0.f, 0.f, 0.f, 0.f};
#pragma unroll
    for (int k = 0; k < D_HID; k++) {
        float2 w = sW[k * 32 + lane];
#pragma unroll
        for (int nn = 0; nn < 4; nn++) {
            float h = sH[warp * 4 + nn][k];
            z0[nn] += h * w.x;
            z1[nn] += h * w.y;
        }
    }

    const float* aggP = (const float*)g_aggP;
    const float* deg  = (const float*)g_deg4;
    float bb0 = b2[lane];
    float bb1 = (lane < 8) ? b2[lane + 32] : 0.0f;

#pragma unroll
    for (int nn = 0; nn < 4; nn++) {
        int node = nodeBase + nn;
        float inv = 1.0f / fmaxf(deg[node], 1.0f);
        float a0 = aggP[node * D_OUT + lane] * inv;
        float a1 = (lane < 8) ? aggP[node * D_OUT + 32 + lane] * inv : 0.0f;

        float v0 = z0[nn] + a0 + bb0;
        float v1 = (lane < 8) ? (z1[nn] + a1 + bb1) : 0.0f;

        float m = (lane < 8) ? fmaxf(v0, v1) : v0;
#pragma unroll
        for (int o = 16; o > 0; o >>= 1) m = fmaxf(m, __shfl_xor_sync(0xffffffffu, m, o));
        float ssum = expf(v0 - m) + ((lane < 8) ? expf(v1 - m) : 0.0f);
#pragma unroll
        for (int o = 16; o > 0; o >>= 1) ssum += __shfl_xor_sync(0xffffffffu, ssum, o);
        float lse = m + logf(ssum);

        out[node * D_OUT + lane] = v0 - lse;
        if (lane < 8) out[node * D_OUT + 32 + lane] = v1 - lse;
    }
}

// ---------------------------------------------------------------------------
extern "C" void kernel_launch(void* const* d_in, const int* in_sizes, int n_in,
                              void* d_out, int out_size) {
    const float* X   = (const float*)d_in[0];
    const int*   A   = (const int*)d_in[1];     // int32 (JAX x64 disabled)
    const float* W   = (const float*)d_in[2];
    const float* Wl1 = (const float*)d_in[3];
    const float* Wr1 = (const float*)d_in[4];
    const float* b1  = (const float*)d_in[5];
    const float* Wl2 = (const float*)d_in[6];
    const float* Wr2 = (const float*)d_in[7];
    const float* b2  = (const float*)d_in[8];
    float*       out = (float*)d_out;

    mask_kernel<<<MASK_N / (256 * 4), 256>>>();
    zero_kernel<<<2048, 256>>>();
    edge1_kernel<<<(N_EDGES * 8) / 256, 256>>>(X, A, W);
    node1_kernel<<<N_NODES / 32, 256>>>(X, Wl1, Wr1, b1);
    pmul_kernel<<<N_NODES / 32, 256>>>(Wl2);
    edge2_kernel<<<(N_EDGES * 16) / 256, 256>>>(A, W);
    node2_kernel<<<N_NODES / 32, 256>>>(Wr2, b2, out);
}

// round 10
// speedup vs baseline: 1.5357x; 1.0749x over previous
#include <cuda_runtime.h>
#include <cstdint>
#include <math.h>

// ----------------------------------------------------------------------------
// GraphSAGE (2-layer weighted-mean SAGEConv) on sm_100a.
// L1: agg1 = sum(w*X[src]); H = dropout(relu(l2norm((agg1/deg)@Wl1 + X@Wr1 + b1)))
// P  = H@Wl2 fused into node1 (linearity: mean(w*H)@Wl2 == mean(w*P))
// L2: aggP = sum(w*P[src]); Z = aggP/deg + H@Wr2 + b2; out = log_softmax(Z)
// A is int32. Dropout = jax partitionable threefry, key(42): counter (0,i),
// word = y0^y1, keep <=> top bit == 0.
// ----------------------------------------------------------------------------

#define N_NODES 100000
#define N_EDGES 1600000
#define D_IN    32
#define D_HID   64
#define D_OUT   40
#define MASK_N  (N_NODES * D_HID)

// Scratch (device globals). float4-typed => 16B aligned.
__device__ float4        g_agg1[N_NODES * (D_IN / 4)];    // 12.8 MB
__device__ float4        g_deg4[N_NODES / 4];             // 0.4 MB
__device__ float4        g_H   [N_NODES * (D_HID / 4)];   // 25.6 MB
__device__ float4        g_P   [N_NODES * 10];            // 16 MB (40 f/node)
__device__ float4        g_aggP[N_NODES * 10];            // 16 MB
__device__ unsigned char g_mask[MASK_N];                  // 6.4 MB

// ---------------------------------------------------------------------------
__device__ __forceinline__ void red_add_v4(float4* p, float4 v) {
    asm volatile(
        "{\n\t"
        ".reg .u64 gp;\n\t"
        "cvta.to.global.u64 gp, %0;\n\t"
        "red.global.add.v4.f32 [gp], {%1, %2, %3, %4};\n\t"
        "}"
        :: "l"(p), "f"(v.x), "f"(v.y), "f"(v.z), "f"(v.w)
        : "memory");
}

// ---------------------------------------------------------------------------
// threefry2x32 partitionable, key (0,42): counter (0,i), word = y0^y1.
// 4 independent chains per thread; one uchar4 store.
// ---------------------------------------------------------------------------
__device__ __forceinline__ uint32_t rotl32(uint32_t x, int r) {
    return __funnelshift_l(x, x, r);
}

__global__ void mask_kernel() {
    int t = blockIdx.x * blockDim.x + threadIdx.x;   // 1.6M threads
    uint32_t base = (uint32_t)t * 4u;
    if (base >= (uint32_t)MASK_N) return;

    const uint32_t ks0 = 0u;
    const uint32_t ks1 = 42u;
    const uint32_t ks2 = 0x1BD11BDAu ^ 0u ^ 42u;

    uint32_t a0 = ks0, a1 = ks0, a2 = ks0, a3 = ks0;
    uint32_t b0 = base + 0u + ks1, b1v = base + 1u + ks1;
    uint32_t b2v = base + 2u + ks1, b3 = base + 3u + ks1;

#define TF4(r) { \
    a0 += b0;  b0  = rotl32(b0,  (r)); b0  ^= a0; \
    a1 += b1v; b1v = rotl32(b1v, (r)); b1v ^= a1; \
    a2 += b2v; b2v = rotl32(b2v, (r)); b2v ^= a2; \
    a3 += b3;  b3  = rotl32(b3,  (r)); b3  ^= a3; }
#define INJ4(ka, kb, c) { \
    a0 += (ka); b0  += (kb) + (c); a1 += (ka); b1v += (kb) + (c); \
    a2 += (ka); b2v += (kb) + (c); a3 += (ka); b3  += (kb) + (c); }

    TF4(13) TF4(15) TF4(26) TF4(6)
    INJ4(ks1, ks2, 1u)
    TF4(17) TF4(29) TF4(16) TF4(24)
    INJ4(ks2, ks0, 2u)
    TF4(13) TF4(15) TF4(26) TF4(6)
    INJ4(ks0, ks1, 3u)
    TF4(17) TF4(29) TF4(16) TF4(24)
    INJ4(ks1, ks2, 4u)
    TF4(13) TF4(15) TF4(26) TF4(6)
    INJ4(ks2, ks0, 5u)
#undef TF4
#undef INJ4

    uchar4 m;
    m.x = (unsigned char)((((a0 ^ b0)  >> 31) ^ 1u) & 1u);
    m.y = (unsigned char)((((a1 ^ b1v) >> 31) ^ 1u) & 1u);
    m.z = (unsigned char)((((a2 ^ b2v) >> 31) ^ 1u) & 1u);
    m.w = (unsigned char)((((a3 ^ b3)  >> 31) ^ 1u) & 1u);
    ((uchar4*)g_mask)[t] = m;
}

// ---------------------------------------------------------------------------
__global__ void zero_kernel() {
    int i      = blockIdx.x * blockDim.x + threadIdx.x;
    int stride = gridDim.x * blockDim.x;
    float4 z = make_float4(0.f, 0.f, 0.f, 0.f);
    for (int j = i; j < 800000;  j += stride) g_agg1[j] = z;
    for (int j = i; j < 1000000; j += stride) g_aggP[j] = z;
    for (int j = i; j < 25000;   j += stride) g_deg4[j] = z;
}

// ---------------------------------------------------------------------------
// layer-1 edge scatter: agg1[dst] += X[src]*w (8 x float4), deg[dst] += 1.
// ---------------------------------------------------------------------------
__global__ void edge1_kernel(const float* __restrict__ X,
                             const int* __restrict__ A,
                             const float* __restrict__ W) {
    int t = blockIdx.x * blockDim.x + threadIdx.x;
    int e = t >> 3;
    int c = t & 7;
    if (e >= N_EDGES) return;
    int lane = threadIdx.x & 31;
    int srcLane = lane & ~7;

    int s = 0, d = 0; float w = 0.f;
    if (c == 0) {
        s = A[e];
        d = A[N_EDGES + e];
        w = W[e];
    }
    s = __shfl_sync(0xffffffffu, s, srcLane);
    d = __shfl_sync(0xffffffffu, d, srcLane);
    w = __shfl_sync(0xffffffffu, w, srcLane);

    float4 xv = ((const float4*)X)[s * 8 + c];
    float4 m = make_float4(xv.x * w, xv.y * w, xv.z * w, xv.w * w);
    red_add_v4(&g_agg1[d * 8 + c], m);
    if (c == 0) atomicAdd((float*)g_deg4 + d, 1.0f);
}

// ---------------------------------------------------------------------------
// Fused layer-1 node update + P projection. 4 nodes/warp, 32 nodes/block.
// Phase A: H = dropout(relu(l2norm((agg1/deg)@Wl1 + X@Wr1 + b1)))  -> g_H, sH
// Phase B: P = H @ Wl2                                             -> g_P
// Input/H shared reads are warp-uniform broadcasts, vectorized to LDS.128.
// ---------------------------------------------------------------------------
__global__ void node1_kernel(const float* __restrict__ X,
                             const float* __restrict__ Wl1,
                             const float* __restrict__ Wr1,
                             const float* __restrict__ b1,
                             const float* __restrict__ Wl2) {
    __shared__ float2 sWl[D_IN * 32];     // [k][j] pairs (j, j+32)   8 KB
    __shared__ float2 sWr[D_IN * 32];     //                          8 KB
    __shared__ float2 sW2[D_HID * 32];    // Wl2 pairs (j, j+32<40?) 16 KB
    __shared__ float2 sIn[32][D_IN];      // [node][k] = (a, x)       8 KB
    __shared__ float  sH [32][D_HID];     // [node][k] = H            8 KB

    int tid  = threadIdx.x;
    int warp = tid >> 5, lane = tid & 31;

    for (int i = tid; i < D_IN * 32; i += 256) {
        int k = i >> 5, j = i & 31;
        sWl[i] = make_float2(Wl1[k * D_HID + j], Wl1[k * D_HID + j + 32]);
        sWr[i] = make_float2(Wr1[k * D_HID + j], Wr1[k * D_HID + j + 32]);
    }
    for (int i = tid; i < D_HID * 32; i += 256) {
        int k = i >> 5, j = i & 31;
        float w0 = Wl2[k * D_OUT + j];
        float w1 = (j + 32 < D_OUT) ? Wl2[k * D_OUT + j + 32] : 0.0f;
        sW2[i] = make_float2(w0, w1);
    }

    int nodeBase = blockIdx.x * 32 + warp * 4;       // grid 3125 -> exact
    const float* agg1 = (const float*)g_agg1;
    const float* deg  = (const float*)g_deg4;

#pragma unroll
    for (int nn = 0; nn < 4; nn++) {
        int node = nodeBase + nn;
        float inv = 1.0f / fmaxf(deg[node], 1.0f);
        float a = agg1[node * D_IN + lane] * inv;
        float x = X[node * D_IN + lane];
        sIn[warp * 4 + nn][lane] = make_float2(a, x);
    }
    __syncthreads();

    // ---- Phase A: acc = a@Wl1 + x@Wr1 + b1 ----
    float bb0 = b1[lane], bb1 = b1[lane + 32];
    float acc0[4], acc1[4];
#pragma unroll
    for (int nn = 0; nn < 4; nn++) { acc0[nn] = bb0; acc1[nn] = bb1; }

#pragma unroll
    for (int k = 0; k < D_IN; k += 2) {
        float2 wl0 = sWl[k * 32 + lane];
        float2 wl1 = sWl[(k + 1) * 32 + lane];
        float2 wr0 = sWr[k * 32 + lane];
        float2 wr1 = sWr[(k + 1) * 32 + lane];
#pragma unroll
        for (int nn = 0; nn < 4; nn++) {
            float4 ax = *(const float4*)&sIn[warp * 4 + nn][k];  // (a0,x0,a1,x1)
            acc0[nn] += ax.x * wl0.x + ax.y * wr0.x + ax.z * wl1.x + ax.w * wr1.x;
            acc1[nn] += ax.x * wl0.y + ax.y * wr0.y + ax.z * wl1.y + ax.w * wr1.y;
        }
    }

    float* H = (float*)g_H;
#pragma unroll
    for (int nn = 0; nn < 4; nn++) {
        float ss = acc0[nn] * acc0[nn] + acc1[nn] * acc1[nn];
#pragma unroll
        for (int o = 16; o > 0; o >>= 1) ss += __shfl_xor_sync(0xffffffffu, ss, o);
        float scale = rsqrtf(fmaxf(ss, 1e-24f));

        float h0 = fmaxf(acc0[nn] * scale, 0.0f);
        float h1 = fmaxf(acc1[nn] * scale, 0.0f);
        int base = (nodeBase + nn) * D_HID;
        h0 = g_mask[base + lane]      ? 2.0f * h0 : 0.0f;
        h1 = g_mask[base + lane + 32] ? 2.0f * h1 : 0.0f;
        H[base + lane]      = h0;
        H[base + lane + 32] = h1;
        sH[warp * 4 + nn][lane]      = h0;
        sH[warp * 4 + nn][lane + 32] = h1;
    }
    __syncwarp();   // sH is warp-private (rows warp*4..warp*4+3)

    // ---- Phase B: P = H @ Wl2 ----
    float p0[4] = {0.f, 0.f, 0.f, 0.f};
    float p1[4] = {0.f, 0.f, 0.f, 0.f};
#pragma unroll
    for (int k = 0; k < D_HID; k += 4) {
        float2 w0 = sW2[(k + 0) * 32 + lane];
        float2 w1 = sW2[(k + 1) * 32 + lane];
        float2 w2 = sW2[(k + 2) * 32 + lane];
        float2 w3 = sW2[(k + 3) * 32 + lane];
#pragma unroll
        for (int nn = 0; nn < 4; nn++) {
            float4 h = *(const float4*)&sH[warp * 4 + nn][k];    // broadcast
            p0[nn] += h.x * w0.x + h.y * w1.x + h.z * w2.x + h.w * w3.x;
            p1[nn] += h.x * w0.y + h.y * w1.y + h.z * w2.y + h.w * w3.y;
        }
    }

    float* P = (float*)g_P;
#pragma unroll
    for (int nn = 0; nn < 4; nn++) {
        int base = (nodeBase + nn) * D_OUT;
        P[base + lane] = p0[nn];
        if (lane < 8) P[base + 32 + lane] = p1[nn];
    }
}

// ---------------------------------------------------------------------------
// layer-2 edge scatter on P: aggP[dst] += P[src]*w. Exact 10 threads/edge,
// no idle lanes; index loads are same-cache-line across an edge's threads.
// ---------------------------------------------------------------------------
__global__ void edge2_kernel(const int* __restrict__ A,
                             const float* __restrict__ W) {
    int t = blockIdx.x * blockDim.x + threadIdx.x;   // 16M threads exact
    int e = t / 10;
    int c = t - e * 10;
    if (e >= N_EDGES) return;

    int   s = A[e];
    int   d = A[N_EDGES + e];
    float w = W[e];

    float4 pv = g_P[s * 10 + c];
    float4 m = make_float4(pv.x * w, pv.y * w, pv.z * w, pv.w * w);
    red_add_v4(&g_aggP[d * 10 + c], m);
}

// ---------------------------------------------------------------------------
// layer-2 node update: Z = aggP/deg + H@Wr2 + b2; out = log_softmax(Z).
// 4 nodes/warp; sH reads broadcast LDS.128.
// ---------------------------------------------------------------------------
__global__ void node2_kernel(const float* __restrict__ Wr2,
                             const float* __restrict__ b2,
                             float* __restrict__ out) {
    __shared__ float2 sW[D_HID * 32];     // Wr2 pairs                16 KB
    __shared__ float  sH[32][D_HID];      //                           8 KB

    int tid  = threadIdx.x;
    int warp = tid >> 5, lane = tid & 31;

    for (int i = tid; i < D_HID * 32; i += 256) {
        int k = i >> 5, j = i & 31;
        float w0 = Wr2[k * D_OUT + j];
        float w1 = (j + 32 < D_OUT) ? Wr2[k * D_OUT + j + 32] : 0.0f;
        sW[i] = make_float2(w0, w1);
    }

    int nodeBase = blockIdx.x * 32 + warp * 4;
    const float* H = (const float*)g_H;
#pragma unroll
    for (int nn = 0; nn < 4; nn++) {
        int node = nodeBase + nn;
        sH[warp * 4 + nn][lane]      = H[node * D_HID + lane];
        sH[warp * 4 + nn][lane + 32] = H[node * D_HID + lane + 32];
    }
    __syncthreads();

    float z0[4] = {0.f, 0.f, 0.f, 0.f};
    float z1[4] = {0.f, 0.f, 0.f, 0.f};
#pragma unroll
    for (int k = 0; k < D_HID; k += 4) {
        float2 w0 = sW[(k + 0) * 32 + lane];
        float2 w1 = sW[(k + 1) * 32 + lane];
        float2 w2 = sW[(k + 2) * 32 + lane];
        float2 w3 = sW[(k + 3) * 32 + lane];
#pragma unroll
        for (int nn = 0; nn < 4; nn++) {
            float4 h = *(const float4*)&sH[warp * 4 + nn][k];    // broadcast
            z0[nn] += h.x * w0.x + h.y * w1.x + h.z * w2.x + h.w * w3.x;
            z1[nn] += h.x * w0.y + h.y * w1.y + h.z * w2.y + h.w * w3.y;
        }
    }

    const float* aggP = (const float*)g_aggP;
    const float* deg  = (const float*)g_deg4;
    float bb0 = b2[lane];
    float bb1 = (lane < 8) ? b2[lane + 32] : 0.0f;

#pragma unroll
    for (int nn = 0; nn < 4; nn++) {
        int node = nodeBase + nn;
        float inv = 1.0f / fmaxf(deg[node], 1.0f);
        float a0 = aggP[node * D_OUT + lane] * inv;
        float a1 = (lane < 8) ? aggP[node * D_OUT + 32 + lane] * inv : 0.0f;

        float v0 = z0[nn] + a0 + bb0;
        float v1 = (lane < 8) ? (z1[nn] + a1 + bb1) : 0.0f;

        float m = (lane < 8) ? fmaxf(v0, v1) : v0;
#pragma unroll
        for (int o = 16; o > 0; o >>= 1) m = fmaxf(m, __shfl_xor_sync(0xffffffffu, m, o));
        float ssum = expf(v0 - m) + ((lane < 8) ? expf(v1 - m) : 0.0f);
#pragma unroll
        for (int o = 16; o > 0; o >>= 1) ssum += __shfl_xor_sync(0xffffffffu, ssum, o);
        float lse = m + logf(ssum);

        out[node * D_OUT + lane] = v0 - lse;
        if (lane < 8) out[node * D_OUT + 32 + lane] = v1 - lse;
    }
}

// ---------------------------------------------------------------------------
extern "C" void kernel_launch(void* const* d_in, const int* in_sizes, int n_in,
                              void* d_out, int out_size) {
    const float* X   = (const float*)d_in[0];
    const int*   A   = (const int*)d_in[1];     // int32 (JAX x64 disabled)
    const float* W   = (const float*)d_in[2];
    const float* Wl1 = (const float*)d_in[3];
    const float* Wr1 = (const float*)d_in[4];
    const float* b1  = (const float*)d_in[5];
    const float* Wl2 = (const float*)d_in[6];
    const float* Wr2 = (const float*)d_in[7];
    const float* b2  = (const float*)d_in[8];
    float*       out = (float*)d_out;

    mask_kernel<<<MASK_N / (256 * 4), 256>>>();
    zero_kernel<<<2048, 256>>>();
    edge1_kernel<<<(N_EDGES * 8) / 256, 256>>>(X, A, W);
    node1_kernel<<<N_NODES / 32, 256>>>(X, Wl1, Wr1, b1, Wl2);
    edge2_kernel<<<(N_EDGES * 10) / 256, 256>>>(A, W);
    node2_kernel<<<N_NODES / 32, 256>>>(Wr2, b2, out);
}

// round 13
// speedup vs baseline: 1.7252x; 1.1234x over previous
#include <cuda_runtime.h>
#include <cstdint>
#include <math.h>

// ----------------------------------------------------------------------------
// GraphSAGE (2-layer weighted-mean SAGEConv) on sm_100a.
// L1: agg1 = sum(w*X[src]); H = dropout(relu(l2norm((agg1/deg)@Wl1 + X@Wr1 + b1)))
// node1 (fused): P = H@Wl2, ZH = H@Wr2      (linearity: mean(w*H)@Wl2 == mean(w*P))
// L2: aggP = sum(w*P[src]); Z = aggP/deg + ZH + b2; out = log_softmax(Z)
// A is int32. Dropout = jax partitionable threefry, key(42): counter (0,i),
// word = y0^y1, keep <=> top bit == 0.
// Phase A and phase B weights share one 32KB smem buffer (48KB static cap).
// ----------------------------------------------------------------------------

#define N_NODES 100000
#define N_EDGES 1600000
#define D_IN    32
#define D_HID   64
#define D_OUT   40
#define MASK_N  (N_NODES * D_HID)

// Scratch (device globals). float4-typed => 16B aligned.
__device__ float4        g_agg1[N_NODES * (D_IN / 4)];    // 12.8 MB
__device__ float4        g_deg4[N_NODES / 4];             // 0.4 MB
__device__ float4        g_P   [N_NODES * 10];            // 16 MB (40 f/node)
__device__ float4        g_ZH  [N_NODES * 10];            // 16 MB
__device__ float4        g_aggP[N_NODES * 10];            // 16 MB
__device__ unsigned char g_mask[MASK_N];                  // 6.4 MB

// ---------------------------------------------------------------------------
__device__ __forceinline__ void red_add_v4(float4* p, float4 v) {
    asm volatile(
        "{\n\t"
        ".reg .u64 gp;\n\t"
        "cvta.to.global.u64 gp, %0;\n\t"
        "red.global.add.v4.f32 [gp], {%1, %2, %3, %4};\n\t"
        "}"
        :: "l"(p), "f"(v.x), "f"(v.y), "f"(v.z), "f"(v.w)
        : "memory");
}

__device__ __forceinline__ uint32_t rotl32(uint32_t x, int r) {
    return __funnelshift_l(x, x, r);
}

// ---------------------------------------------------------------------------
// init: threefry mask (4 chains/thread) + zero accumulators, one launch.
// ---------------------------------------------------------------------------
__global__ void init_kernel() {
    int t = blockIdx.x * blockDim.x + threadIdx.x;   // 1.6M threads
    uint32_t base = (uint32_t)t * 4u;

    if (base < (uint32_t)MASK_N) {
        const uint32_t ks0 = 0u;
        const uint32_t ks1 = 42u;
        const uint32_t ks2 = 0x1BD11BDAu ^ 0u ^ 42u;

        uint32_t a0 = ks0, a1 = ks0, a2 = ks0, a3 = ks0;
        uint32_t b0 = base + 0u + ks1, b1v = base + 1u + ks1;
        uint32_t b2v = base + 2u + ks1, b3 = base + 3u + ks1;

#define TF4(r) { \
    a0 += b0;  b0  = rotl32(b0,  (r)); b0  ^= a0; \
    a1 += b1v; b1v = rotl32(b1v, (r)); b1v ^= a1; \
    a2 += b2v; b2v = rotl32(b2v, (r)); b2v ^= a2; \
    a3 += b3;  b3  = rotl32(b3,  (r)); b3  ^= a3; }
#define INJ4(ka, kb, c) { \
    a0 += (ka); b0  += (kb) + (c); a1 += (ka); b1v += (kb) + (c); \
    a2 += (ka); b2v += (kb) + (c); a3 += (ka); b3  += (kb) + (c); }

        TF4(13) TF4(15) TF4(26) TF4(6)
        INJ4(ks1, ks2, 1u)
        TF4(17) TF4(29) TF4(16) TF4(24)
        INJ4(ks2, ks0, 2u)
        TF4(13) TF4(15) TF4(26) TF4(6)
        INJ4(ks0, ks1, 3u)
        TF4(17) TF4(29) TF4(16) TF4(24)
        INJ4(ks1, ks2, 4u)
        TF4(13) TF4(15) TF4(26) TF4(6)
        INJ4(ks2, ks0, 5u)
#undef TF4
#undef INJ4

        uchar4 m;
        m.x = (unsigned char)((((a0 ^ b0)  >> 31) ^ 1u) & 1u);
        m.y = (unsigned char)((((a1 ^ b1v) >> 31) ^ 1u) & 1u);
        m.z = (unsigned char)((((a2 ^ b2v) >> 31) ^ 1u) & 1u);
        m.w = (unsigned char)((((a3 ^ b3)  >> 31) ^ 1u) & 1u);
        ((uchar4*)g_mask)[t] = m;
    }

    // zeroing (grid-stride; 1.6M threads)
    int stride = gridDim.x * blockDim.x;
    float4 z = make_float4(0.f, 0.f, 0.f, 0.f);
    for (int j = t; j < 800000;  j += stride) g_agg1[j] = z;
    for (int j = t; j < 1000000; j += stride) g_aggP[j] = z;
    for (int j = t; j < 25000;   j += stride) g_deg4[j] = z;
}

// ---------------------------------------------------------------------------
// layer-1 edge scatter: agg1[dst] += X[src]*w (8 x float4), deg[dst] += 1.
// ---------------------------------------------------------------------------
__global__ void edge1_kernel(const float* __restrict__ X,
                             const int* __restrict__ A,
                             const float* __restrict__ W) {
    int t = blockIdx.x * blockDim.x + threadIdx.x;
    int e = t >> 3;
    int c = t & 7;
    if (e >= N_EDGES) return;
    int lane = threadIdx.x & 31;
    int srcLane = lane & ~7;

    int s = 0, d = 0; float w = 0.f;
    if (c == 0) {
        s = A[e];
        d = A[N_EDGES + e];
        w = W[e];
    }
    s = __shfl_sync(0xffffffffu, s, srcLane);
    d = __shfl_sync(0xffffffffu, d, srcLane);
    w = __shfl_sync(0xffffffffu, w, srcLane);

    float4 xv = ((const float4*)X)[s * 8 + c];
    float4 m = make_float4(xv.x * w, xv.y * w, xv.z * w, xv.w * w);
    red_add_v4(&g_agg1[d * 8 + c], m);
    if (c == 0) atomicAdd((float*)g_deg4 + d, 1.0f);
}

// ---------------------------------------------------------------------------
// Fused node kernel: 4 nodes/warp, 32 nodes/block, grid 3125.
//  Phase A: H = dropout(relu(l2norm((agg1/deg)@Wl1 + X@Wr1 + b1)))
//  Phase B: P = H@Wl2 -> g_P ; ZH = H@Wr2 -> g_ZH
// One 32KB weight buffer, reloaded between phases (L2-resident reads).
// sBuf row (per node): phase A holds (a0,x0,a1,x1,...); phase B holds H[64].
// ---------------------------------------------------------------------------
__global__ __launch_bounds__(256) void node1_kernel(
        const float* __restrict__ X,
        const float* __restrict__ Wl1,
        const float* __restrict__ Wr1,
        const float* __restrict__ b1,
        const float* __restrict__ Wl2,
        const float* __restrict__ Wr2) {
    __shared__ float4 sW[2048];                 // 32 KB, overlaid A/B weights
    __shared__ float  sBuf[32][D_HID];          // inputs then H, 8 KB

    int tid  = threadIdx.x;
    int warp = tid >> 5, lane = tid & 31;

    // Phase-A weights: sW[k*32+j] = (wl_j, wl_j32, wr_j, wr_j32), k<32
    for (int i = tid; i < D_IN * 32; i += 256) {
        int k = i >> 5, j = i & 31;
        sW[i] = make_float4(Wl1[k * D_HID + j], Wl1[k * D_HID + j + 32],
                            Wr1[k * D_HID + j], Wr1[k * D_HID + j + 32]);
    }

    int nodeBase = blockIdx.x * 32 + warp * 4;       // grid 3125 -> exact
    const float* agg1 = (const float*)g_agg1;
    const float* deg  = (const float*)g_deg4;

    // stage inputs: sBuf[row][2k]=a_k, [2k+1]=x_k  (k = lane)
#pragma unroll
    for (int nn = 0; nn < 4; nn++) {
        int node = nodeBase + nn;
        float inv = 1.0f / fmaxf(deg[node], 1.0f);
        float a = agg1[node * D_IN + lane] * inv;
        float x = X[node * D_IN + lane];
        *(float2*)&sBuf[warp * 4 + nn][2 * lane] = make_float2(a, x);
    }
    __syncthreads();

    // ---- Phase A ----
    float acc0[4], acc1[4];
    {
        float bb0 = b1[lane], bb1 = b1[lane + 32];
#pragma unroll
        for (int nn = 0; nn < 4; nn++) { acc0[nn] = bb0; acc1[nn] = bb1; }
    }
#pragma unroll
    for (int k2 = 0; k2 < D_IN / 2; k2++) {
        float4 wa = sW[(2 * k2) * 32 + lane];
        float4 wb = sW[(2 * k2 + 1) * 32 + lane];
#pragma unroll
        for (int nn = 0; nn < 4; nn++) {
            float4 ax = *(const float4*)&sBuf[warp * 4 + nn][4 * k2]; // a0,x0,a1,x1
            acc0[nn] += ax.x * wa.x + ax.y * wa.z + ax.z * wb.x + ax.w * wb.z;
            acc1[nn] += ax.x * wa.y + ax.y * wa.w + ax.z * wb.y + ax.w * wb.w;
        }
    }
    __syncthreads();   // everyone done reading phase-A weights

    // Reload sW with phase-B weights:
    //  sW[0..1023]    : Wl2, 2 k per float4:  (w2[2m][j], w2[2m][j+32], w2[2m+1][j], w2[2m+1][j+32])
    //  sW[1024..2047] : Wr2, same packing
    for (int i = tid; i < (D_HID / 2) * 32; i += 256) {
        int k2 = i >> 5, j = i & 31;
        bool hi = (j + 32 < D_OUT);
        sW[i]        = make_float4(Wl2[(2 * k2) * D_OUT + j],
                                   hi ? Wl2[(2 * k2) * D_OUT + j + 32] : 0.f,
                                   Wl2[(2 * k2 + 1) * D_OUT + j],
                                   hi ? Wl2[(2 * k2 + 1) * D_OUT + j + 32] : 0.f);
        sW[1024 + i] = make_float4(Wr2[(2 * k2) * D_OUT + j],
                                   hi ? Wr2[(2 * k2) * D_OUT + j + 32] : 0.f,
                                   Wr2[(2 * k2 + 1) * D_OUT + j],
                                   hi ? Wr2[(2 * k2 + 1) * D_OUT + j + 32] : 0.f);
    }

    // norm + relu + dropout; H overwrites sBuf rows (warp-private rows)
#pragma unroll
    for (int nn = 0; nn < 4; nn++) {
        float ss = acc0[nn] * acc0[nn] + acc1[nn] * acc1[nn];
#pragma unroll
        for (int o = 16; o > 0; o >>= 1) ss += __shfl_xor_sync(0xffffffffu, ss, o);
        float scale = rsqrtf(fmaxf(ss, 1e-24f));

        float h0 = fmaxf(acc0[nn] * scale, 0.0f);
        float h1 = fmaxf(acc1[nn] * scale, 0.0f);
        int mbase = (nodeBase + nn) * D_HID;
        h0 = g_mask[mbase + lane]      ? 2.0f * h0 : 0.0f;
        h1 = g_mask[mbase + lane + 32] ? 2.0f * h1 : 0.0f;
        sBuf[warp * 4 + nn][lane]      = h0;
        sBuf[warp * 4 + nn][lane + 32] = h1;
    }
    __syncthreads();   // weights loaded + H in place

    // ---- Phase B: P = H@Wl2, ZH = H@Wr2 (shared H broadcasts reused) ----
    float p0[4] = {0.f, 0.f, 0.f, 0.f}, p1[4] = {0.f, 0.f, 0.f, 0.f};
    float q0[4] = {0.f, 0.f, 0.f, 0.f}, q1[4] = {0.f, 0.f, 0.f, 0.f};
#pragma unroll
    for (int m = 0; m < D_HID / 4; m++) {        // 4 k per iter
        float4 w2a = sW[(2 * m) * 32 + lane];
        float4 w2b = sW[(2 * m + 1) * 32 + lane];
        float4 wra = sW[1024 + (2 * m) * 32 + lane];
        float4 wrb = sW[1024 + (2 * m + 1) * 32 + lane];
#pragma unroll
        for (int nn = 0; nn < 4; nn++) {
            float4 h = *(const float4*)&sBuf[warp * 4 + nn][4 * m];
            p0[nn] += h.x * w2a.x + h.y * w2a.z + h.z * w2b.x + h.w * w2b.z;
            p1[nn] += h.x * w2a.y + h.y * w2a.w + h.z * w2b.y + h.w * w2b.w;
            q0[nn] += h.x * wra.x + h.y * wra.z + h.z * wrb.x + h.w * wrb.z;
            q1[nn] += h.x * wra.y + h.y * wra.w + h.z * wrb.y + h.w * wrb.w;
        }
    }

    float* P  = (float*)g_P;
    float* ZH = (float*)g_ZH;
#pragma unroll
    for (int nn = 0; nn < 4; nn++) {
        int base = (nodeBase + nn) * D_OUT;
        P[base + lane]  = p0[nn];
        ZH[base + lane] = q0[nn];
        if (lane < 8) {
            P[base + 32 + lane]  = p1[nn];
            ZH[base + 32 + lane] = q1[nn];
        }
    }
}

// ---------------------------------------------------------------------------
// layer-2 edge scatter on P: aggP[dst] += P[src]*w. Exact 10 threads/edge.
// ---------------------------------------------------------------------------
__global__ void edge2_kernel(const int* __restrict__ A,
                             const float* __restrict__ W) {
    int t = blockIdx.x * blockDim.x + threadIdx.x;   // 16M threads exact
    int e = t / 10;
    int c = t - e * 10;
    if (e >= N_EDGES) return;

    int   s = A[e];
    int   d = A[N_EDGES + e];
    float w = W[e];

    float4 pv = g_P[s * 10 + c];
    float4 m = make_float4(pv.x * w, pv.y * w, pv.z * w, pv.w * w);
    red_add_v4(&g_aggP[d * 10 + c], m);
}

// ---------------------------------------------------------------------------
// layer-2 finish: Z = aggP/deg + ZH + b2; out = log_softmax(Z).
// Pure elementwise + warp softmax. 4 nodes/warp.
// ---------------------------------------------------------------------------
__global__ void node2_kernel(const float* __restrict__ b2,
                             float* __restrict__ out) {
    int tid  = threadIdx.x;
    int warp = tid >> 5, lane = tid & 31;
    int nodeBase = blockIdx.x * 32 + warp * 4;

    const float* aggP = (const float*)g_aggP;
    const float* ZH   = (const float*)g_ZH;
    const float* deg  = (const float*)g_deg4;
    float bb0 = b2[lane];
    float bb1 = (lane < 8) ? b2[lane + 32] : 0.0f;

#pragma unroll
    for (int nn = 0; nn < 4; nn++) {
        int node = nodeBase + nn;
        float inv = 1.0f / fmaxf(deg[node], 1.0f);
        int base = node * D_OUT;

        float v0 = aggP[base + lane] * inv + ZH[base + lane] + bb0;
        float v1 = (lane < 8)
                 ? aggP[base + 32 + lane] * inv + ZH[base + 32 + lane] + bb1
                 : 0.0f;

        float m = (lane < 8) ? fmaxf(v0, v1) : v0;
#pragma unroll
        for (int o = 16; o > 0; o >>= 1) m = fmaxf(m, __shfl_xor_sync(0xffffffffu, m, o));
        float ssum = expf(v0 - m) + ((lane < 8) ? expf(v1 - m) : 0.0f);
#pragma unroll
        for (int o = 16; o > 0; o >>= 1) ssum += __shfl_xor_sync(0xffffffffu, ssum, o);
        float lse = m + logf(ssum);

        out[base + lane] = v0 - lse;
        if (lane < 8) out[base + 32 + lane] = v1 - lse;
    }
}

// ---------------------------------------------------------------------------
extern "C" void kernel_launch(void* const* d_in, const int* in_sizes, int n_in,
                              void* d_out, int out_size) {
    const float* X   = (const float*)d_in[0];
    const int*   A   = (const int*)d_in[1];     // int32 (JAX x64 disabled)
    const float* W   = (const float*)d_in[2];
    const float* Wl1 = (const float*)d_in[3];
    const float* Wr1 = (const float*)d_in[4];
    const float* b1  = (const float*)d_in[5];
    const float* Wl2 = (const float*)d_in[6];
    const float* Wr2 = (const float*)d_in[7];
    const float* b2  = (const float*)d_in[8];
    float*       out = (float*)d_out;

    init_kernel<<<MASK_N / (256 * 4), 256>>>();
    edge1_kernel<<<(N_EDGES * 8) / 256, 256>>>(X, A, W);
    node1_kernel<<<N_NODES / 32, 256>>>(X, Wl1, Wr1, b1, Wl2, Wr2);
    edge2_kernel<<<(N_EDGES * 10) / 256, 256>>>(A, W);
    node2_kernel<<<N_NODES / 32, 256>>>(b2, out);
}